// round 9
// baseline (speedup 1.0000x reference)
#include <cuda_runtime.h>
#include <cuda_fp16.h>
#include <math.h>
#include <stdint.h>

#define N_NODES 4096
#define IN_F    512
#define NHEAD   8
#define DHEAD   64
#define CTOT    512
#define NB_CAP  128

// Scratch (static device globals — no runtime allocation)
__device__ __half g_mxh[N_NODES * CTOT];   // x @ W in fp16 (4 MB, L2-resident)
__device__ float  g_wt [CTOT * IN_F];      // W^T K-major tf32 (1 MB)
__device__ float  g_wexp[N_NODES * NHEAD]; // exp weights (128 KB)

// ---------------- helpers ----------------
__device__ __forceinline__ uint32_t smem_u32(const void* p) {
    return (uint32_t)__cvta_generic_to_shared(p);
}
__device__ __forceinline__ void cpa16(uint32_t saddr, const float* g) {
    asm volatile("cp.async.cg.shared.global [%0], [%1], 16;\n" :: "r"(saddr), "l"(g));
}
__device__ __forceinline__ float tf32r(float v) {
    uint32_t r;
    asm("cvt.rna.tf32.f32 %0, %1;" : "=r"(r) : "f"(v));
    return __uint_as_float(r);
}
__device__ __forceinline__ void mma_tf32(float* c, const uint32_t* a, const uint32_t* b) {
    asm volatile(
        "mma.sync.aligned.m16n8k8.row.col.f32.tf32.tf32.f32 "
        "{%0,%1,%2,%3}, {%4,%5,%6,%7}, {%8,%9}, {%0,%1,%2,%3};"
        : "+f"(c[0]), "+f"(c[1]), "+f"(c[2]), "+f"(c[3])
        : "r"(a[0]), "r"(a[1]), "r"(a[2]), "r"(a[3]), "r"(b[0]), "r"(b[1]));
}
__device__ __forceinline__ void ffma2(unsigned long long& d,
                                      unsigned long long a,
                                      unsigned long long b) {
    asm("fma.rn.f32x2 %0, %1, %2, %0;" : "+l"(d) : "l"(a), "l"(b));
}
__device__ __forceinline__ unsigned long long pack_dup(float x) {
    unsigned long long r;
    unsigned u = __float_as_uint(x);
    asm("mov.b64 %0, {%1, %1};" : "=l"(r) : "r"(u));
    return r;
}
__device__ __forceinline__ unsigned long long packf2(float2 f) {
    unsigned long long r;
    asm("mov.b64 %0, {%1, %2};" : "=l"(r)
        : "r"(__float_as_uint(f.x)), "r"(__float_as_uint(f.y)));
    return r;
}
__device__ __forceinline__ float2 unpack2(unsigned long long v) {
    unsigned lo, hi;
    asm("mov.b64 {%0, %1}, %2;" : "=r"(lo), "=r"(hi) : "l"(v));
    return make_float2(__uint_as_float(lo), __uint_as_float(hi));
}

// ---------------------------------------------------------------------------
// Prep: g_wt[c][f] = round_tf32(W[c>>6][f][c&63])
// ---------------------------------------------------------------------------
__global__ __launch_bounds__(256) void prep_kernel(const float* __restrict__ W)
{
    __shared__ float t[64][65];
    const int h  = blockIdx.x >> 3;
    const int f0 = (blockIdx.x & 7) * 64;
    const float* Wb = W + (size_t)h * IN_F * DHEAD + (size_t)f0 * DHEAD;
    for (int e = threadIdx.x; e < 4096; e += 256) {
        int i = e >> 6, d = e & 63;
        t[i][d] = Wb[i * 64 + d];
    }
    __syncthreads();
    for (int e = threadIdx.x; e < 4096; e += 256) {
        int d = e >> 6, i = e & 63;
        g_wt[(size_t)(h * 64 + d) * IN_F + f0 + i] = tf32r(t[i][d]);
    }
}

// ---------------------------------------------------------------------------
// Kernel 1: mx = x @ wt^T via mma.sync m16n8k8 tf32.
// CTA tile 64x128 (grid 64x4 = 256 blocks), 256 threads, 8 warps (2x4),
// 32x32 warp tiles. smem 30KB -> 2-3 CTAs/SM, all 148 SMs busy.
// ---------------------------------------------------------------------------
#define KT 16
#define NKT (IN_F / KT)   // 32

__global__ __launch_bounds__(256) void gemm_mx_kernel(const float* __restrict__ x)
{
    __shared__ float As[2][64][20];
    __shared__ float Bs[2][128][20];

    const int tid  = threadIdx.x;
    const int wid  = tid >> 5, lane = tid & 31;
    const int wm   = wid >> 2, wn = wid & 3;        // 2 x 4 warp grid
    const int g    = lane >> 2, t4 = lane & 3;
    const int m0   = blockIdx.x * 64;
    const int c0   = blockIdx.y * 128;

    const uint32_t as_b = smem_u32(&As[0][0][0]);
    const uint32_t bs_b = smem_u32(&Bs[0][0][0]);

    float acc[2][4][4];
    #pragma unroll
    for (int mt = 0; mt < 2; mt++)
        #pragma unroll
        for (int nt = 0; nt < 4; nt++)
            #pragma unroll
            for (int q = 0; q < 4; q++) acc[mt][nt][q] = 0.f;

    const float* arow = x    + (size_t)m0 * IN_F;
    const float* brow = g_wt + (size_t)c0 * IN_F;

    auto fill = [&](int s, int t) {
        const int f0 = t * KT;
        {   // A: 64 rows x 16 k = 256 float4, 1 per thread
            int row = tid >> 2, kc = (tid & 3) * 4;
            uint32_t off = (uint32_t)(((s * 64 + row) * 20 + kc) * 4);
            cpa16(as_b + off, arow + (size_t)row * IN_F + f0 + kc);
        }
        #pragma unroll
        for (int l = 0; l < 2; l++) {   // B: 128 rows x 16 k = 512 float4
            int idx = tid + l * 256;
            int row = idx >> 2, kc = (idx & 3) * 4;
            uint32_t off = (uint32_t)(((s * 128 + row) * 20 + kc) * 4);
            cpa16(bs_b + off, brow + (size_t)row * IN_F + f0 + kc);
        }
    };

    fill(0, 0);
    asm volatile("cp.async.commit_group;" ::: "memory");

    for (int t = 0; t < NKT; t++) {
        const int s = t & 1;
        if (t + 1 < NKT) {
            fill(s ^ 1, t + 1);
            asm volatile("cp.async.commit_group;" ::: "memory");
            asm volatile("cp.async.wait_group 1;" ::: "memory");
        } else {
            asm volatile("cp.async.wait_group 0;" ::: "memory");
        }
        __syncthreads();

        #pragma unroll
        for (int ks = 0; ks < 2; ks++) {
            const int kb = ks * 8;
            uint32_t af[2][4];
            #pragma unroll
            for (int mt = 0; mt < 2; mt++) {
                int m = wm * 32 + mt * 16 + g;
                af[mt][0] = __float_as_uint(As[s][m    ][kb + t4]);
                af[mt][1] = __float_as_uint(As[s][m + 8][kb + t4]);
                af[mt][2] = __float_as_uint(As[s][m    ][kb + t4 + 4]);
                af[mt][3] = __float_as_uint(As[s][m + 8][kb + t4 + 4]);
            }
            uint32_t bf[4][2];
            #pragma unroll
            for (int nt = 0; nt < 4; nt++) {
                int n = wn * 32 + nt * 8 + g;
                bf[nt][0] = __float_as_uint(Bs[s][n][kb + t4]);
                bf[nt][1] = __float_as_uint(Bs[s][n][kb + t4 + 4]);
            }
            #pragma unroll
            for (int mt = 0; mt < 2; mt++)
                #pragma unroll
                for (int nt = 0; nt < 4; nt++)
                    mma_tf32(acc[mt][nt], af[mt], bf[nt]);
        }
        __syncthreads();
    }

    // epilogue: write fp16
    #pragma unroll
    for (int mt = 0; mt < 2; mt++) {
        #pragma unroll
        for (int nt = 0; nt < 4; nt++) {
            int row = m0 + wm * 32 + mt * 16 + g;
            int col = c0 + wn * 32 + nt * 8 + t4 * 2;
            *(__half2*)(g_mxh + (size_t)row * CTOT + col) =
                __floats2half2_rn(acc[mt][nt][0], acc[mt][nt][1]);
            *(__half2*)(g_mxh + (size_t)(row + 8) * CTOT + col) =
                __floats2half2_rn(acc[mt][nt][2], acc[mt][nt][3]);
        }
    }
}

// ---------------------------------------------------------------------------
// Kernel 2: g_wexp[n,h] = exp(mx[n,h,:] . a_dst[h,:])
// (a_origin source term cancels in the row softmax)
// ---------------------------------------------------------------------------
__global__ __launch_bounds__(256) void wexp_kernel(const float* __restrict__ a_dst)
{
    const int gw   = blockIdx.x * 8 + (threadIdx.x >> 5);
    const int lane = threadIdx.x & 31;
    const int n    = gw >> 2;
    const int hp   = gw & 3;
    const int head = 2 * hp + (lane >> 4);

    uint2 raw = __ldg((const uint2*)(g_mxh + (size_t)n * CTOT + hp * 128 + lane * 4));
    float2 v0 = __half22float2(*(__half2*)&raw.x);
    float2 v1 = __half22float2(*(__half2*)&raw.y);
    float4 a  = __ldg((const float4*)(a_dst + head * DHEAD + (lane & 15) * 4));
    float t = v0.x * a.x + v0.y * a.y + v1.x * a.z + v1.y * a.w;
    #pragma unroll
    for (int o = 8; o > 0; o >>= 1) t += __shfl_xor_sync(0xFFFFFFFFu, t, o);
    if ((lane & 15) == 0) g_wexp[n * NHEAD + head] = expf(t);
}

// ---------------------------------------------------------------------------
// Kernel 3: out[i,c] = sum_{j in adj(i)} w[j,h] mx[j,c] / sum_j w[j,h]
// One block (128 thr) per row. Phase A: R6-style ordered compaction (loads
// inline in the scan loop, 32 regs -> full occupancy). Phase B: 64 channel-
// groups x 2 neighbor sub-streams, f32x2 accumulation.
// ---------------------------------------------------------------------------
#define SEG_CAP 96

__device__ __forceinline__ void accp(unsigned long long* a2, uint4 r,
                                     unsigned long long wp) {
    ffma2(a2[0], packf2(__half22float2(*(__half2*)&r.x)), wp);
    ffma2(a2[1], packf2(__half22float2(*(__half2*)&r.y)), wp);
    ffma2(a2[2], packf2(__half22float2(*(__half2*)&r.z)), wp);
    ffma2(a2[3], packf2(__half22float2(*(__half2*)&r.w)), wp);
}

__global__ __launch_bounds__(128) void aggregate_kernel(
    const float* __restrict__ adj, float* __restrict__ out)
{
    __shared__ unsigned short seg[4][SEG_CAP];
    __shared__ int cnts[4], nb_sh;
    __shared__ int offs[4];
    __shared__ unsigned short ulist[NB_CAP];
    __shared__ float wsh[NB_CAP][NHEAD];
    __shared__ float pac[64][9];
    __shared__ float pden1[64];

    const int i    = blockIdx.x;
    const int tid  = threadIdx.x;
    const int warp = tid >> 5;
    const int lane = tid & 31;

    // ---- Phase A: ordered compaction (loads inline -> low reg pressure) ----
    {
        const float* arow = adj + (size_t)i * N_NODES + warp * 1024;
        int cnt = 0;
        #pragma unroll
        for (int p = 0; p < 8; p++) {
            int col = p * 128 + lane * 4;
            float4 v = __ldg((const float4*)(arow + col));
            unsigned m4 = (v.x > 0.f ? 1u : 0u) | (v.y > 0.f ? 2u : 0u)
                        | (v.z > 0.f ? 4u : 0u) | (v.w > 0.f ? 8u : 0u);
            int c = __popc(m4), inc = c;
            #pragma unroll
            for (int d2 = 1; d2 < 32; d2 <<= 1) {
                int t = __shfl_up_sync(0xFFFFFFFFu, inc, d2);
                if (lane >= d2) inc += t;
            }
            int pos = cnt + inc - c;
            int base = warp * 1024 + col;
            #pragma unroll
            for (int b = 0; b < 4; b++)
                if ((m4 >> b) & 1u) seg[warp][pos++] = (unsigned short)(base + b);
            cnt += __shfl_sync(0xFFFFFFFFu, inc, 31);
        }
        if (lane == 0) cnts[warp] = cnt;
    }
    __syncthreads();
    if (tid == 0) {
        int s = 0;
        #pragma unroll
        for (int w = 0; w < 4; w++) { offs[w] = s; s += cnts[w]; }
        nb_sh = s;
    }
    __syncthreads();
    {
        const int o = offs[warp], cw = cnts[warp];
        for (int k = lane; k < cw; k += 32) ulist[o + k] = seg[warp][k];
        for (int idx = lane; idx < cw * NHEAD; idx += 32) {
            int k = idx >> 3, h2 = idx & 7;
            wsh[o + k][h2] = __ldg(g_wexp + (int)seg[warp][k] * NHEAD + h2);
        }
    }
    __syncthreads();

    // ---- Phase B: f32x2 accumulation ----
    const int nb  = nb_sh;
    const int cg  = tid & 63;            // channels [cg*8, cg*8+8)
    const int sub = tid >> 6;            // neighbors k === sub (mod 2)
    const int h   = cg >> 3;
    const __half* base = g_mxh + cg * 8;

    unsigned long long acc2[4] = {0ull, 0ull, 0ull, 0ull};
    float den = 0.f;
    int k = sub;
    for (; k + 6 < nb; k += 8) {
        int j0 = ulist[k], j1 = ulist[k + 2], j2 = ulist[k + 4], j3 = ulist[k + 6];
        uint4 r0 = __ldg((const uint4*)(base + (size_t)j0 * CTOT));
        uint4 r1 = __ldg((const uint4*)(base + (size_t)j1 * CTOT));
        uint4 r2 = __ldg((const uint4*)(base + (size_t)j2 * CTOT));
        uint4 r3 = __ldg((const uint4*)(base + (size_t)j3 * CTOT));
        float w0 = wsh[k][h], w1 = wsh[k + 2][h], w2 = wsh[k + 4][h], w3 = wsh[k + 6][h];
        accp(acc2, r0, pack_dup(w0));
        accp(acc2, r1, pack_dup(w1));
        accp(acc2, r2, pack_dup(w2));
        accp(acc2, r3, pack_dup(w3));
        den += w0; den += w1; den += w2; den += w3;
    }
    for (; k < nb; k += 2) {
        int j0 = ulist[k];
        uint4 r0 = __ldg((const uint4*)(base + (size_t)j0 * CTOT));
        float w0 = wsh[k][h];
        accp(acc2, r0, pack_dup(w0));
        den += w0;
    }

    float accf[8];
    #pragma unroll
    for (int q = 0; q < 4; q++) {
        float2 f = unpack2(acc2[q]);
        accf[2 * q] = f.x; accf[2 * q + 1] = f.y;
    }

    if (sub == 1) {
        #pragma unroll
        for (int q = 0; q < 8; q++) pac[cg][q] = accf[q];
        pden1[cg] = den;
    }
    __syncthreads();
    if (sub == 0) {
        den += pden1[cg];
        float inv = 1.f / den;
        float* op = out + (size_t)i * CTOT + cg * 8;
        *(float4*)(op) = make_float4((accf[0] + pac[cg][0]) * inv,
                                     (accf[1] + pac[cg][1]) * inv,
                                     (accf[2] + pac[cg][2]) * inv,
                                     (accf[3] + pac[cg][3]) * inv);
        *(float4*)(op + 4) = make_float4((accf[4] + pac[cg][4]) * inv,
                                         (accf[5] + pac[cg][5]) * inv,
                                         (accf[6] + pac[cg][6]) * inv,
                                         (accf[7] + pac[cg][7]) * inv);
    }
}

// ---------------------------------------------------------------------------
// Inputs: x[4096,512], adj[4096,4096], W[8,512,64], a_origin[8,64] (cancels),
//         a_dst[8,64].  Output: float32 [4096, 512]
// ---------------------------------------------------------------------------
extern "C" void kernel_launch(void* const* d_in, const int* in_sizes, int n_in,
                              void* d_out, int out_size)
{
    const float* x     = (const float*)d_in[0];
    const float* adj   = (const float*)d_in[1];
    const float* W     = (const float*)d_in[2];
    const float* a_dst = (const float*)d_in[4];
    float* out = (float*)d_out;

    prep_kernel<<<64, 256>>>(W);
    gemm_mx_kernel<<<dim3(64, 4), 256>>>(x);
    wexp_kernel<<<2048, 256>>>(a_dst);
    aggregate_kernel<<<N_NODES, 128>>>(adj, out);
}

// round 10
// speedup vs baseline: 1.2668x; 1.2668x over previous
#include <cuda_runtime.h>
#include <cuda_fp16.h>
#include <math.h>
#include <stdint.h>

#define N_NODES 4096
#define IN_F    512
#define NHEAD   8
#define DHEAD   64
#define CTOT    512
#define NB_CAP  128

// Scratch (static device globals — no runtime allocation)
__device__ __half g_mxh[N_NODES * CTOT];   // x @ W in fp16 (4 MB, L2-resident)
__device__ __half g_xh [N_NODES * IN_F];   // x in fp16 (4 MB)
__device__ __half g_wth[CTOT * IN_F];      // W^T K-major fp16 (0.5 MB)
__device__ float  g_wexp[N_NODES * NHEAD]; // exp weights (128 KB)

// ---------------- helpers ----------------
__device__ __forceinline__ uint32_t smem_u32(const void* p) {
    return (uint32_t)__cvta_generic_to_shared(p);
}
__device__ __forceinline__ void cpa16(uint32_t saddr, const void* g) {
    asm volatile("cp.async.cg.shared.global [%0], [%1], 16;\n" :: "r"(saddr), "l"(g));
}
// mma m16n8k16 fp16 inputs, fp32 accumulate
__device__ __forceinline__ void mma_f16(float* c, const uint32_t* a, const uint32_t* b) {
    asm volatile(
        "mma.sync.aligned.m16n8k16.row.col.f32.f16.f16.f32 "
        "{%0,%1,%2,%3}, {%4,%5,%6,%7}, {%8,%9}, {%0,%1,%2,%3};"
        : "+f"(c[0]), "+f"(c[1]), "+f"(c[2]), "+f"(c[3])
        : "r"(a[0]), "r"(a[1]), "r"(a[2]), "r"(a[3]), "r"(b[0]), "r"(b[1]));
}

// ---------------------------------------------------------------------------
// Prep: blocks [0,1024): g_xh = fp16(x)  (8 floats / thread)
//       blocks [1024,1088): g_wth[c][f] = fp16(W[c>>6][f][c&63]) (transpose)
// ---------------------------------------------------------------------------
__global__ __launch_bounds__(256) void prep_kernel(const float* __restrict__ x,
                                                   const float* __restrict__ W)
{
    if (blockIdx.x < 1024) {
        int i = (blockIdx.x * 256 + threadIdx.x) * 8;
        float4 v0 = __ldg((const float4*)(x + i));
        float4 v1 = __ldg((const float4*)(x + i + 4));
        __half2 h[4];
        h[0] = __floats2half2_rn(v0.x, v0.y);
        h[1] = __floats2half2_rn(v0.z, v0.w);
        h[2] = __floats2half2_rn(v1.x, v1.y);
        h[3] = __floats2half2_rn(v1.z, v1.w);
        *(uint4*)(g_xh + i) = *(uint4*)h;
    } else {
        __shared__ float t[64][65];
        const int b  = blockIdx.x - 1024;
        const int h  = b >> 3;
        const int f0 = (b & 7) * 64;
        const float* Wb = W + (size_t)h * IN_F * DHEAD + (size_t)f0 * DHEAD;
        for (int e = threadIdx.x; e < 4096; e += 256) {
            int i = e >> 6, d = e & 63;
            t[i][d] = Wb[i * 64 + d];
        }
        __syncthreads();
        for (int e = threadIdx.x; e < 4096; e += 256) {
            int d = e >> 6, i = e & 63;
            g_wth[(size_t)(h * 64 + d) * IN_F + f0 + i] = __float2half_rn(t[i][d]);
        }
    }
}

// ---------------------------------------------------------------------------
// Kernel 1: mx = x @ W  via mma.sync m16n8k16 fp16 (fp32 accum).
// CTA 64x128 (grid 64x4), 256 threads, 8 warps (2x4), 32x32 warp tiles.
// KT=32 halves per k-tile (2 MMA k-steps), double-buffered cp.async.
// Epilogue ALSO computes g_wexp = exp(mx . a_dst) block-locally (each block
// fully contains 2 heads over its 64 rows) from fp32 accumulators.
// ---------------------------------------------------------------------------
#define KT  32
#define NKT (IN_F / KT)   // 16
#define APAD 40           // halves per row (32 data + 8 pad) -> conflict-free

__global__ __launch_bounds__(256) void gemm_mx_kernel(const float* __restrict__ a_dst)
{
    __shared__ __half As[2][64][APAD];
    __shared__ __half Bs[2][128][APAD];
    __shared__ float  adst_sh[2][64];
    __shared__ float  swex[64][2];

    const int tid  = threadIdx.x;
    const int wid  = tid >> 5, lane = tid & 31;
    const int wm   = wid >> 2, wn = wid & 3;        // 2 x 4 warp grid
    const int g    = lane >> 2, t4 = lane & 3;
    const int m0   = blockIdx.x * 64;
    const int c0   = blockIdx.y * 128;

    // load a_dst slice for this block's 2 heads
    if (tid < 128)
        adst_sh[tid >> 6][tid & 63] =
            __ldg(a_dst + (size_t)(blockIdx.y * 2 + (tid >> 6)) * DHEAD + (tid & 63));

    const uint32_t as_b = smem_u32(&As[0][0][0]);
    const uint32_t bs_b = smem_u32(&Bs[0][0][0]);

    float acc[2][4][4];
    #pragma unroll
    for (int mt = 0; mt < 2; mt++)
        #pragma unroll
        for (int nt = 0; nt < 4; nt++)
            #pragma unroll
            for (int q = 0; q < 4; q++) acc[mt][nt][q] = 0.f;

    const __half* arow = g_xh  + (size_t)m0 * IN_F;
    const __half* brow = g_wth + (size_t)c0 * IN_F;

    auto fill = [&](int s, int t) {
        const int f0 = t * KT;
        {   // A: 64 rows x 4 chunks of 8 halves = 256 ops
            int row = tid >> 2, ch = tid & 3;
            uint32_t off = (uint32_t)((s * 64 + row) * (APAD * 2) + ch * 16);
            cpa16(as_b + off, arow + (size_t)row * IN_F + f0 + ch * 8);
        }
        #pragma unroll
        for (int l = 0; l < 2; l++) {   // B: 128 rows x 4 chunks = 512 ops
            int idx = tid + l * 256;
            int row = idx >> 2, ch = idx & 3;
            uint32_t off = (uint32_t)((s * 128 + row) * (APAD * 2) + ch * 16);
            cpa16(bs_b + off, brow + (size_t)row * IN_F + f0 + ch * 8);
        }
    };

    fill(0, 0);
    asm volatile("cp.async.commit_group;" ::: "memory");

    for (int t = 0; t < NKT; t++) {
        const int s = t & 1;
        if (t + 1 < NKT) {
            fill(s ^ 1, t + 1);
            asm volatile("cp.async.commit_group;" ::: "memory");
            asm volatile("cp.async.wait_group 1;" ::: "memory");
        } else {
            asm volatile("cp.async.wait_group 0;" ::: "memory");
        }
        __syncthreads();

        #pragma unroll
        for (int ks = 0; ks < 2; ks++) {
            const int kb = ks * 16;     // halves
            uint32_t af[2][4];
            #pragma unroll
            for (int mt = 0; mt < 2; mt++) {
                int m = wm * 32 + mt * 16 + g;
                af[mt][0] = *(const uint32_t*)&As[s][m    ][kb + t4 * 2];
                af[mt][1] = *(const uint32_t*)&As[s][m + 8][kb + t4 * 2];
                af[mt][2] = *(const uint32_t*)&As[s][m    ][kb + t4 * 2 + 8];
                af[mt][3] = *(const uint32_t*)&As[s][m + 8][kb + t4 * 2 + 8];
            }
            uint32_t bf[4][2];
            #pragma unroll
            for (int nt = 0; nt < 4; nt++) {
                int n = wn * 32 + nt * 8 + g;
                bf[nt][0] = *(const uint32_t*)&Bs[s][n][kb + t4 * 2];
                bf[nt][1] = *(const uint32_t*)&Bs[s][n][kb + t4 * 2 + 8];
            }
            #pragma unroll
            for (int mt = 0; mt < 2; mt++)
                #pragma unroll
                for (int nt = 0; nt < 4; nt++)
                    mma_f16(acc[mt][nt], af[mt], bf[nt]);
        }
        __syncthreads();
    }

    // ---- epilogue 1: write mxh fp16 ----
    #pragma unroll
    for (int mt = 0; mt < 2; mt++) {
        #pragma unroll
        for (int nt = 0; nt < 4; nt++) {
            int row = m0 + wm * 32 + mt * 16 + g;
            int col = c0 + wn * 32 + nt * 8 + t4 * 2;
            *(__half2*)(g_mxh + (size_t)row * CTOT + col) =
                __floats2half2_rn(acc[mt][nt][0], acc[mt][nt][1]);
            *(__half2*)(g_mxh + (size_t)(row + 8) * CTOT + col) =
                __floats2half2_rn(acc[mt][nt][2], acc[mt][nt][3]);
        }
    }

    // ---- epilogue 2: fused wexp. warp covers rows [wm*32,+32), head wn>>1,
    //      col-half wn&1. partial over its 32 cols, reduced over t4 quad. ----
    const int hloc = wn >> 1;
    const int chalf = (wn & 1) * 32;
    float sp[2][2];   // [mt][hi]  rows g(+8)
    #pragma unroll
    for (int mt = 0; mt < 2; mt++) {
        #pragma unroll
        for (int hi = 0; hi < 2; hi++) {
            float sv = 0.f;
            #pragma unroll
            for (int nt = 0; nt < 4; nt++) {
                int cb = chalf + nt * 8 + t4 * 2;
                sv += acc[mt][nt][hi * 2 + 0] * adst_sh[hloc][cb];
                sv += acc[mt][nt][hi * 2 + 1] * adst_sh[hloc][cb + 1];
            }
            sv += __shfl_xor_sync(0xFFFFFFFFu, sv, 1);
            sv += __shfl_xor_sync(0xFFFFFFFFu, sv, 2);
            sp[mt][hi] = sv;
        }
    }
    if ((wn & 1) == 0 && t4 == 0) {
        #pragma unroll
        for (int mt = 0; mt < 2; mt++)
            #pragma unroll
            for (int hi = 0; hi < 2; hi++)
                swex[wm * 32 + mt * 16 + hi * 8 + g][hloc] = sp[mt][hi];
    }
    __syncthreads();
    if ((wn & 1) == 1 && t4 == 0) {
        #pragma unroll
        for (int mt = 0; mt < 2; mt++)
            #pragma unroll
            for (int hi = 0; hi < 2; hi++) {
                int r = wm * 32 + mt * 16 + hi * 8 + g;
                float tot = swex[r][hloc] + sp[mt][hi];
                g_wexp[(size_t)(m0 + r) * NHEAD + blockIdx.y * 2 + hloc] = expf(tot);
            }
    }
}

// ---------------------------------------------------------------------------
// Kernel 2: out[i,c] = sum_{j in adj(i)} w[j,h] mx[j,c] / sum_j w[j,h]
// (exact R6 aggregate — measured 31.3us) One block (128 thr) per row.
// ---------------------------------------------------------------------------
#define SEG_CAP 96

__device__ __forceinline__ void acc8(float* acc, uint4 r, float w) {
    float2 f0 = __half22float2(*(__half2*)&r.x);
    float2 f1 = __half22float2(*(__half2*)&r.y);
    float2 f2 = __half22float2(*(__half2*)&r.z);
    float2 f3 = __half22float2(*(__half2*)&r.w);
    acc[0] += f0.x * w; acc[1] += f0.y * w;
    acc[2] += f1.x * w; acc[3] += f1.y * w;
    acc[4] += f2.x * w; acc[5] += f2.y * w;
    acc[6] += f3.x * w; acc[7] += f3.y * w;
}

__global__ __launch_bounds__(128) void aggregate_kernel(
    const float* __restrict__ adj, float* __restrict__ out)
{
    __shared__ unsigned short seg[4][SEG_CAP];
    __shared__ int cnts[4], nb_sh;
    __shared__ int offs[4];
    __shared__ unsigned short ulist[NB_CAP];
    __shared__ float wsh[NB_CAP][NHEAD];
    __shared__ float pac[64][9];
    __shared__ float pden1[64];

    const int i    = blockIdx.x;
    const int tid  = threadIdx.x;
    const int warp = tid >> 5;
    const int lane = tid & 31;

    // ---- Phase A: ordered compaction, warp w covers cols [w*1024,(w+1)*1024) ----
    {
        const float* arow = adj + (size_t)i * N_NODES + warp * 1024;
        int cnt = 0;
        #pragma unroll
        for (int p = 0; p < 8; p++) {
            int col = p * 128 + lane * 4;
            float4 v = __ldg((const float4*)(arow + col));
            unsigned m4 = (v.x > 0.f ? 1u : 0u) | (v.y > 0.f ? 2u : 0u)
                        | (v.z > 0.f ? 4u : 0u) | (v.w > 0.f ? 8u : 0u);
            int c = __popc(m4), inc = c;
            #pragma unroll
            for (int d2 = 1; d2 < 32; d2 <<= 1) {
                int t = __shfl_up_sync(0xFFFFFFFFu, inc, d2);
                if (lane >= d2) inc += t;
            }
            int pos = cnt + inc - c;
            int base = warp * 1024 + col;
            #pragma unroll
            for (int b = 0; b < 4; b++)
                if ((m4 >> b) & 1u) seg[warp][pos++] = (unsigned short)(base + b);
            cnt += __shfl_sync(0xFFFFFFFFu, inc, 31);
        }
        if (lane == 0) cnts[warp] = cnt;
    }
    __syncthreads();
    if (tid == 0) {
        int s = 0;
        #pragma unroll
        for (int w = 0; w < 4; w++) { offs[w] = s; s += cnts[w]; }
        nb_sh = s;
    }
    __syncthreads();
    {
        const int o = offs[warp], cw = cnts[warp];
        for (int k = lane; k < cw; k += 32) ulist[o + k] = seg[warp][k];
        for (int idx = lane; idx < cw * NHEAD; idx += 32) {
            int k = idx >> 3, h2 = idx & 7;
            wsh[o + k][h2] = __ldg(g_wexp + (size_t)seg[warp][k] * NHEAD + h2);
        }
    }
    __syncthreads();

    // ---- Phase B: fp32 accumulation (R6 body) ----
    const int nb  = nb_sh;
    const int cg  = tid & 63;            // channels [cg*8, cg*8+8)
    const int sub = tid >> 6;            // neighbors k === sub (mod 2)
    const int h   = cg >> 3;
    const __half* base = g_mxh + cg * 8;

    float acc[8] = {0.f, 0.f, 0.f, 0.f, 0.f, 0.f, 0.f, 0.f};
    float den = 0.f;
    int k = sub;
    for (; k + 6 < nb; k += 8) {
        int j0 = ulist[k], j1 = ulist[k + 2], j2 = ulist[k + 4], j3 = ulist[k + 6];
        uint4 r0 = __ldg((const uint4*)(base + (size_t)j0 * CTOT));
        uint4 r1 = __ldg((const uint4*)(base + (size_t)j1 * CTOT));
        uint4 r2 = __ldg((const uint4*)(base + (size_t)j2 * CTOT));
        uint4 r3 = __ldg((const uint4*)(base + (size_t)j3 * CTOT));
        float w0 = wsh[k][h], w1 = wsh[k + 2][h], w2 = wsh[k + 4][h], w3 = wsh[k + 6][h];
        acc8(acc, r0, w0); acc8(acc, r1, w1); acc8(acc, r2, w2); acc8(acc, r3, w3);
        den += w0; den += w1; den += w2; den += w3;
    }
    for (; k < nb; k += 2) {
        int j0 = ulist[k];
        uint4 r0 = __ldg((const uint4*)(base + (size_t)j0 * CTOT));
        float w0 = wsh[k][h];
        acc8(acc, r0, w0);
        den += w0;
    }

    if (sub == 1) {
        #pragma unroll
        for (int q = 0; q < 8; q++) pac[cg][q] = acc[q];
        pden1[cg] = den;
    }
    __syncthreads();
    if (sub == 0) {
        den += pden1[cg];
        float inv = 1.f / den;
        float* op = out + (size_t)i * CTOT + cg * 8;
        *(float4*)(op) = make_float4((acc[0] + pac[cg][0]) * inv,
                                     (acc[1] + pac[cg][1]) * inv,
                                     (acc[2] + pac[cg][2]) * inv,
                                     (acc[3] + pac[cg][3]) * inv);
        *(float4*)(op + 4) = make_float4((acc[4] + pac[cg][4]) * inv,
                                         (acc[5] + pac[cg][5]) * inv,
                                         (acc[6] + pac[cg][6]) * inv,
                                         (acc[7] + pac[cg][7]) * inv);
    }
}

// ---------------------------------------------------------------------------
// Inputs: x[4096,512], adj[4096,4096], W[8,512,64], a_origin[8,64] (cancels),
//         a_dst[8,64].  Output: float32 [4096, 512]
// ---------------------------------------------------------------------------
extern "C" void kernel_launch(void* const* d_in, const int* in_sizes, int n_in,
                              void* d_out, int out_size)
{
    const float* x     = (const float*)d_in[0];
    const float* adj   = (const float*)d_in[1];
    const float* W     = (const float*)d_in[2];
    const float* a_dst = (const float*)d_in[4];
    float* out = (float*)d_out;

    prep_kernel<<<1088, 256>>>(x, W);
    gemm_mx_kernel<<<dim3(64, 4), 256>>>(a_dst);
    aggregate_kernel<<<N_NODES, 128>>>(adj, out);
}